// round 5
// baseline (speedup 1.0000x reference)
#include <cuda_runtime.h>

#define Bb 8
#define Nn 1024
#define Ee 10
#define NCH 32       // j-chunks in colsum
#define JS 4         // j-splits in the iteration matmul
#define JCH 256      // j per split
#define RB 16        // rows per CTA in mm
#define NRB (Nn/RB)  // 64 rowblocks

__device__ float g_Ppart[Bb * NCH * Nn];
__device__ float g_Mpart[Bb * NCH * Nn];
__device__ float g_base[Bb * Nn * Ee];
__device__ float g_h[2][Bb * Ee * Nn];            // ping-pong, [b][e][i]
__device__ float g_part[Bb * NRB * JS * RB * Ee]; // [b][rb][js][r][e]
__device__ int   g_cnt[4 * Bb * NRB];             // per-iteration counters
__device__ float g_S[Bb * Ee];
__device__ float g_wp[Ee * Ee];

__device__ __forceinline__ void ffma2(unsigned long long& acc,
                                      unsigned long long a,
                                      unsigned long long b) {
    asm("fma.rn.f32x2 %0, %1, %2, %0;" : "+l"(acc) : "l"(a), "l"(b));
}

// ---------------------------------------------------------------------------
// Kernel A: column sums of max(w,0)/min(w,0) over source nodes j. Stages Wp.
// ---------------------------------------------------------------------------
__global__ void __launch_bounds__(256) colsum_kernel(
    const float4* __restrict__ w4, const float* __restrict__ wp)
{
    int i4 = threadIdx.x;
    int jc = blockIdx.x;
    int b  = blockIdx.y;
    if (jc == 0 && b == 0 && threadIdx.x < Ee * Ee)
        g_wp[threadIdx.x] = wp[threadIdx.x];

    const float4* p = w4 + ((size_t)(b * Nn + jc * 32) * 256) + i4;
    float4 sp = make_float4(0.f, 0.f, 0.f, 0.f);
    float4 sm = make_float4(0.f, 0.f, 0.f, 0.f);
#pragma unroll 8
    for (int j = 0; j < 32; j++) {
        float4 v = p[(size_t)j * 256];
        sp.x += fmaxf(v.x, 0.f); sm.x += fminf(v.x, 0.f);
        sp.y += fmaxf(v.y, 0.f); sm.y += fminf(v.y, 0.f);
        sp.z += fmaxf(v.z, 0.f); sm.z += fminf(v.z, 0.f);
        sp.w += fmaxf(v.w, 0.f); sm.w += fminf(v.w, 0.f);
    }
    ((float4*)g_Ppart)[(b * NCH + jc) * 256 + i4] = sp;
    ((float4*)g_Mpart)[(b * NCH + jc) * 256 + i4] = sm;
}

// ---------------------------------------------------------------------------
// Kernel B: reduce partials, base, emb1=relu(base), h1=Wp@emb1; zero S & cnt.
// ---------------------------------------------------------------------------
__global__ void __launch_bounds__(256) base_kernel(
    const float* __restrict__ feat,
    const float* __restrict__ ws,
    const float* __restrict__ wnb,
    const float* __restrict__ ew)
{
    int idx = blockIdx.x * 256 + threadIdx.x;
    int b = idx >> 10, i = idx & 1023;
    if (idx < Bb * Ee) g_S[idx] = 0.f;
    if (idx < 4 * Bb * NRB) g_cnt[idx] = 0;

    float P = 0.f, M = 0.f;
#pragma unroll 8
    for (int c = 0; c < NCH; c++) {
        P += g_Ppart[(b * NCH + c) * Nn + i];
        M += g_Mpart[(b * NCH + c) * Nn + i];
    }
    float f = feat[idx];

    float ewv[Ee];
#pragma unroll
    for (int e = 0; e < Ee; e++) ewv[e] = ew[e];

    float emb1[Ee];
#pragma unroll
    for (int e = 0; e < Ee; e++) {
        float cP = 0.f, cM = 0.f;
#pragma unroll
        for (int g = 0; g < Ee; g++) {
            float wv = wnb[e * Ee + g];
            cP += wv * fmaxf(ewv[g], 0.f);
            cM += wv * fminf(ewv[g], 0.f);
        }
        float basev = f * ws[e] + cP * P + cM * M;
        g_base[idx * Ee + e] = basev;
        emb1[e] = fmaxf(basev, 0.f);
    }
#pragma unroll
    for (int e = 0; e < Ee; e++) {
        float hv = 0.f;
#pragma unroll
        for (int g = 0; g < Ee; g++) hv += g_wp[e * Ee + g] * emb1[g];
        g_h[0][(b * Ee + e) * Nn + i] = hv;
    }
}

// ---------------------------------------------------------------------------
// Kernel C: one iteration = partial matmul + last-CTA fused epilogue.
// grid (NRB, JS, Bb) = 2048 CTAs x 128 thr. Warp = 4 groups of 8 lanes,
// group = 1 row over 256 j. FFMA2 accumulators, LDG.128/LDS.128.
// ---------------------------------------------------------------------------
__global__ void __launch_bounds__(128, 7) iter_kernel(
    const float* __restrict__ A,
    int src, int it,
    float* __restrict__ emb_out,
    int last)
{
    __shared__ __align__(16) float sh[Ee * JCH];   // 10 KB h chunk [e][j]
    __shared__ float semb[RB][Ee];
    __shared__ int s_ticket;
    int rb = blockIdx.x, js = blockIdx.y, b = blockIdx.z;
    int tid = threadIdx.x;

    // stage h chunk: sh[e][q] = g_h[src][b][e][js*256+q]
    const float4* hsrc = (const float4*)(g_h[src] + (size_t)b * Ee * Nn);
    float4* sh4 = (float4*)sh;
#pragma unroll
    for (int m = tid; m < Ee * 64; m += 128) {
        int e = m >> 6, q = m & 63;
        sh4[m] = hsrc[e * 256 + js * 64 + q];
    }
    __syncthreads();

    int warp = tid >> 5, lane = tid & 31;
    int g = lane >> 3, sub = lane & 7;
    int r = warp * 4 + g;            // 0..15
    int i = rb * RB + r;

    const float4* Arow =
        (const float4*)(A + (size_t)(b * Nn + i) * Nn) + js * 64 + sub;
    const float4* shp = (const float4*)sh + sub;

    unsigned long long acc[Ee];
#pragma unroll
    for (int e = 0; e < Ee; e++) acc[e] = 0ull;

#pragma unroll 4
    for (int k = 0; k < 8; k++) {
        float4 a = Arow[k * 8];
        ulonglong2 a2 = *reinterpret_cast<ulonglong2*>(&a);
#pragma unroll
        for (int e = 0; e < Ee; e++) {
            float4 h4 = shp[e * 64 + k * 8];
            ulonglong2 h2 = *reinterpret_cast<ulonglong2*>(&h4);
            ffma2(acc[e], a2.x, h2.x);
            ffma2(acc[e], a2.y, h2.y);
        }
    }

    // fold halves + 3-level butterfly within the 8-lane group
    float red[Ee];
#pragma unroll
    for (int e = 0; e < Ee; e++) {
        float2 p = *reinterpret_cast<float2*>(&acc[e]);
        float v = p.x + p.y;
        v += __shfl_xor_sync(0xffffffffu, v, 4);
        v += __shfl_xor_sync(0xffffffffu, v, 2);
        v += __shfl_xor_sync(0xffffffffu, v, 1);
        red[e] = v;
    }

    // store partials: [b][rb][js][r][e], spread over sub-lanes
    float* pp = g_part + (((size_t)(b * NRB + rb) * JS + js) * RB + r) * Ee;
    pp[sub] = red[sub];
    if (sub < 2) pp[sub + 8] = red[sub + 8];

    __threadfence();
    __syncthreads();
    if (tid == 0)
        s_ticket = atomicAdd(&g_cnt[(it * Bb + b) * NRB + rb], 1);
    __syncthreads();
    if (s_ticket != JS - 1) return;     // uniform across CTA

    // ---- fused epilogue for this rowblock (L2-hot partials) ----
    const float* pbase = g_part + ((size_t)(b * NRB + rb) * JS) * RB * Ee;
    for (int t = tid; t < RB * Ee; t += 128) {
        int rr = t / Ee, e = t - rr * Ee;
        float v = g_base[(size_t)(b * Nn + rb * RB + rr) * Ee + e];
#pragma unroll
        for (int j2 = 0; j2 < JS; j2++)
            v += __ldcg(&pbase[(j2 * RB + rr) * Ee + e]);
        semb[rr][e] = fmaxf(v, 0.f);
    }
    __syncthreads();

    float* hout = g_h[src ^ 1] + (size_t)b * Ee * Nn;
    for (int t = tid; t < RB * Ee; t += 128) {
        int rr = t / Ee, e = t - rr * Ee;
        float hv = 0.f;
#pragma unroll
        for (int f = 0; f < Ee; f++)
            hv = fmaf(g_wp[e * Ee + f], semb[rr][f], hv);
        hout[(size_t)e * Nn + rb * RB + rr] = hv;
        if (last)
            emb_out[(size_t)(b * Nn + rb * RB + rr) * Ee + e] = semb[rr][e];
    }

    if (last) {
        __syncthreads();
        if (tid < Ee) {
            float s = 0.f;
#pragma unroll
            for (int rr = 0; rr < RB; rr++) s += semb[rr][tid];
            atomicAdd(&g_S[b * Ee + tid], s);
        }
    }
}

// ---------------------------------------------------------------------------
// Kernel D: q[b,i] = c_b + sum_e d_e * emb[b,i,e]
// ---------------------------------------------------------------------------
__global__ void __launch_bounds__(128) final_kernel(
    const float* __restrict__ emb,
    float* __restrict__ q,
    const float* __restrict__ wqr,
    const float* __restrict__ wall,
    const float* __restrict__ wact)
{
    int idx = blockIdx.x * 128 + threadIdx.x;
    int b = idx >> 10;
    float cb = 0.f;
#pragma unroll
    for (int f = 0; f < Ee; f++) {
        float t = 0.f;
#pragma unroll
        for (int e = 0; e < Ee; e++) t += wall[f * Ee + e] * g_S[b * Ee + e];
        cb += wqr[f] * t;
    }
    float qv = cb;
#pragma unroll
    for (int e = 0; e < Ee; e++) {
        float t = 0.f;
#pragma unroll
        for (int f = 0; f < Ee; f++) t += wqr[Ee + f] * wact[f * Ee + e];
        qv += t * emb[(size_t)idx * Ee + e];
    }
    q[idx] = qv;
}

extern "C" void kernel_launch(void* const* d_in, const int* in_sizes, int n_in,
                              void* d_out, int out_size) {
    const float* features       = (const float*)d_in[0];
    const float* weights        = (const float*)d_in[1];
    const float* adjacency      = (const float*)d_in[2];
    const float* w_selected     = (const float*)d_in[3];
    const float* w_nbpriors     = (const float*)d_in[4];
    const float* w_nbweights    = (const float*)d_in[5];
    const float* w_nbweights_ew = (const float*)d_in[6];
    const float* w_q_reduc      = (const float*)d_in[7];
    const float* w_q_allembed   = (const float*)d_in[8];
    const float* w_q_action     = (const float*)d_in[9];

    float* out = (float*)d_out;
    float* q = out;                  // [B,N]
    float* emb_out = out + Bb * Nn;  // [B,N,E]

    colsum_kernel<<<dim3(NCH, Bb), 256>>>((const float4*)weights, w_nbpriors);
    base_kernel<<<32, 256>>>(features, w_selected, w_nbweights, w_nbweights_ew);

    dim3 ig(NRB, JS, Bb);            // 2048 CTAs
    iter_kernel<<<ig, 128>>>(adjacency, 0, 0, emb_out, 0);  // iter 2
    iter_kernel<<<ig, 128>>>(adjacency, 1, 1, emb_out, 0);  // iter 3
    iter_kernel<<<ig, 128>>>(adjacency, 0, 2, emb_out, 0);  // iter 4
    iter_kernel<<<ig, 128>>>(adjacency, 1, 3, emb_out, 1);  // iter 5 (last)

    final_kernel<<<64, 128>>>(emb_out, q, w_q_reduc, w_q_allembed, w_q_action);
}

// round 6
// speedup vs baseline: 1.4422x; 1.4422x over previous
#include <cuda_runtime.h>

#define Bb 8
#define Nn 1024
#define Ee 10
#define NCH 32   // j-chunks in colsum

__device__ float g_Ppart[Bb * NCH * Nn];
__device__ float g_Mpart[Bb * NCH * Nn];
__device__ float g_base[Bb * Nn * Ee];
__device__ float g_h[2][Bb * Ee * Nn];   // ping-pong, transposed [b][e][i]
__device__ float g_S[Bb * Ee];
__device__ float g_wp[Ee * Ee];

// ---------------------------------------------------------------------------
// Kernel A: column sums of max(w,0)/min(w,0) over source nodes j. Stages Wp.
// ---------------------------------------------------------------------------
__global__ void __launch_bounds__(256) colsum_kernel(
    const float4* __restrict__ w4, const float* __restrict__ wp)
{
    int i4 = threadIdx.x;
    int jc = blockIdx.x;
    int b  = blockIdx.y;
    if (jc == 0 && b == 0 && threadIdx.x < Ee * Ee)
        g_wp[threadIdx.x] = wp[threadIdx.x];

    const float4* p = w4 + ((size_t)(b * Nn + jc * 32) * 256) + i4;
    float4 sp = make_float4(0.f, 0.f, 0.f, 0.f);
    float4 sm = make_float4(0.f, 0.f, 0.f, 0.f);
#pragma unroll 8
    for (int j = 0; j < 32; j++) {
        float4 v = p[(size_t)j * 256];
        sp.x += fmaxf(v.x, 0.f); sm.x += fminf(v.x, 0.f);
        sp.y += fmaxf(v.y, 0.f); sm.y += fminf(v.y, 0.f);
        sp.z += fmaxf(v.z, 0.f); sm.z += fminf(v.z, 0.f);
        sp.w += fmaxf(v.w, 0.f); sm.w += fminf(v.w, 0.f);
    }
    ((float4*)g_Ppart)[(b * NCH + jc) * 256 + i4] = sp;
    ((float4*)g_Mpart)[(b * NCH + jc) * 256 + i4] = sm;
}

// ---------------------------------------------------------------------------
// Kernel B: reduce partials, base, emb1=relu(base), h1=Wp@emb1; zero g_S.
// ---------------------------------------------------------------------------
__global__ void __launch_bounds__(256) base_kernel(
    const float* __restrict__ feat,
    const float* __restrict__ ws,
    const float* __restrict__ wnb,
    const float* __restrict__ ew)
{
    int idx = blockIdx.x * 256 + threadIdx.x;
    int b = idx >> 10, i = idx & 1023;
    if (idx < Bb * Ee) g_S[idx] = 0.f;

    float P = 0.f, M = 0.f;
#pragma unroll 8
    for (int c = 0; c < NCH; c++) {
        P += g_Ppart[(b * NCH + c) * Nn + i];
        M += g_Mpart[(b * NCH + c) * Nn + i];
    }
    float f = feat[idx];

    float ewv[Ee];
#pragma unroll
    for (int e = 0; e < Ee; e++) ewv[e] = ew[e];

    float emb1[Ee];
#pragma unroll
    for (int e = 0; e < Ee; e++) {
        float cP = 0.f, cM = 0.f;
#pragma unroll
        for (int g = 0; g < Ee; g++) {
            float wv = wnb[e * Ee + g];
            cP += wv * fmaxf(ewv[g], 0.f);
            cM += wv * fminf(ewv[g], 0.f);
        }
        float basev = f * ws[e] + cP * P + cM * M;
        g_base[idx * Ee + e] = basev;
        emb1[e] = fmaxf(basev, 0.f);
    }
#pragma unroll
    for (int e = 0; e < Ee; e++) {
        float hv = 0.f;
#pragma unroll
        for (int g = 0; g < Ee; g++) hv += g_wp[e * Ee + g] * emb1[g];
        g_h[0][(b * Ee + e) * Nn + i] = hv;
    }
}

// ---------------------------------------------------------------------------
// Kernel C: one propagation iteration. R1 structure, grid doubled.
//   Block = 128 thr (4 warps); warp = 4 rows x 32 lanes (lane = float4 of j).
//   Full h (40 KB) in smem. grid (64, Bb) = 512 CTAs.
//   A loads are LDG.128, k-loop unrolled x2 => 8 LDG.128 in flight.
// ---------------------------------------------------------------------------
__global__ void __launch_bounds__(128, 5) iter_kernel(
    const float* __restrict__ A,
    int src,
    float* __restrict__ emb_out,
    int last)
{
    __shared__ __align__(16) float sh[Ee * Nn];   // 40 KB h slice [e][j]
    __shared__ float wps[Ee * Ee];
    __shared__ float semb[16][Ee];
    int b = blockIdx.y;
    int tid = threadIdx.x;

    const float* hin = g_h[src];
    float* hout = g_h[src ^ 1];

    // stage full h[b] into smem (2560 float4, 20 per thread)
    const float4* hsrc = (const float4*)(hin + (size_t)b * Ee * Nn);
    float4* hdst = (float4*)sh;
#pragma unroll
    for (int k = 0; k < 20; k++) hdst[tid + k * 128] = hsrc[tid + k * 128];
    if (tid < Ee * Ee) wps[tid] = g_wp[tid];
    __syncthreads();

    int warp = tid >> 5, lane = tid & 31;
    int r0 = blockIdx.x * 16 + warp * 4;          // first of this warp's 4 rows

    const float4* Arow = (const float4*)(A + (size_t)(b * Nn + r0) * Nn) + lane;
    const float4* shp = (const float4*)sh + lane;

    float acc[4][Ee];
#pragma unroll
    for (int r = 0; r < 4; r++)
#pragma unroll
        for (int e = 0; e < Ee; e++) acc[r][e] = 0.f;

#pragma unroll 2
    for (int k = 0; k < 8; k++) {
        int jj = k * 32;                           // float4 column base
        float4 a0 = Arow[0 * 256 + jj];
        float4 a1 = Arow[1 * 256 + jj];
        float4 a2 = Arow[2 * 256 + jj];
        float4 a3 = Arow[3 * 256 + jj];
#pragma unroll
        for (int e = 0; e < Ee; e++) {
            float4 h4 = shp[e * 256 + jj];
            acc[0][e] = fmaf(a0.x, h4.x, acc[0][e]);
            acc[0][e] = fmaf(a0.y, h4.y, acc[0][e]);
            acc[0][e] = fmaf(a0.z, h4.z, acc[0][e]);
            acc[0][e] = fmaf(a0.w, h4.w, acc[0][e]);
            acc[1][e] = fmaf(a1.x, h4.x, acc[1][e]);
            acc[1][e] = fmaf(a1.y, h4.y, acc[1][e]);
            acc[1][e] = fmaf(a1.z, h4.z, acc[1][e]);
            acc[1][e] = fmaf(a1.w, h4.w, acc[1][e]);
            acc[2][e] = fmaf(a2.x, h4.x, acc[2][e]);
            acc[2][e] = fmaf(a2.y, h4.y, acc[2][e]);
            acc[2][e] = fmaf(a2.z, h4.z, acc[2][e]);
            acc[2][e] = fmaf(a2.w, h4.w, acc[2][e]);
            acc[3][e] = fmaf(a3.x, h4.x, acc[3][e]);
            acc[3][e] = fmaf(a3.y, h4.y, acc[3][e]);
            acc[3][e] = fmaf(a3.z, h4.z, acc[3][e]);
            acc[3][e] = fmaf(a3.w, h4.w, acc[3][e]);
        }
    }

    // 5-level butterfly; all lanes end with the row sums
#pragma unroll
    for (int r = 0; r < 4; r++)
#pragma unroll
        for (int e = 0; e < Ee; e++) {
            float v = acc[r][e];
            v += __shfl_xor_sync(0xffffffffu, v, 16);
            v += __shfl_xor_sync(0xffffffffu, v, 8);
            v += __shfl_xor_sync(0xffffffffu, v, 4);
            v += __shfl_xor_sync(0xffffffffu, v, 2);
            v += __shfl_xor_sync(0xffffffffu, v, 1);
            acc[r][e] = v;
        }

    // epilogue: lanes 0..9 each own one e; spread rows over lanes
    if (lane < Ee) {
        int e = lane;
#pragma unroll
        for (int r = 0; r < 4; r++) {
            int i = r0 + r;
            float embf[Ee];
#pragma unroll
            for (int f = 0; f < Ee; f++)
                embf[f] = fmaxf(g_base[(size_t)(b * Nn + i) * Ee + f] + acc[r][f], 0.f);
            float hv = 0.f;
#pragma unroll
            for (int f = 0; f < Ee; f++) hv = fmaf(wps[e * Ee + f], embf[f], hv);
            hout[(size_t)(b * Ee + e) * Nn + i] = hv;
            if (last) {
                emb_out[(size_t)(b * Nn + i) * Ee + e] = embf[e];
                semb[warp * 4 + r][e] = embf[e];
            }
        }
    }

    if (last) {
        __syncthreads();
        if (tid < Ee) {
            float s = 0.f;
#pragma unroll
            for (int rr = 0; rr < 16; rr++) s += semb[rr][tid];
            atomicAdd(&g_S[b * Ee + tid], s);
        }
    }
}

// ---------------------------------------------------------------------------
// Kernel D: q[b,i] = c_b + sum_e d_e * emb[b,i,e]
// ---------------------------------------------------------------------------
__global__ void __launch_bounds__(128) final_kernel(
    const float* __restrict__ emb,
    float* __restrict__ q,
    const float* __restrict__ wqr,
    const float* __restrict__ wall,
    const float* __restrict__ wact)
{
    int idx = blockIdx.x * 128 + threadIdx.x;
    int b = idx >> 10;
    float cb = 0.f;
#pragma unroll
    for (int f = 0; f < Ee; f++) {
        float t = 0.f;
#pragma unroll
        for (int e = 0; e < Ee; e++) t += wall[f * Ee + e] * g_S[b * Ee + e];
        cb += wqr[f] * t;
    }
    float qv = cb;
#pragma unroll
    for (int e = 0; e < Ee; e++) {
        float t = 0.f;
#pragma unroll
        for (int f = 0; f < Ee; f++) t += wqr[Ee + f] * wact[f * Ee + e];
        qv += t * emb[(size_t)idx * Ee + e];
    }
    q[idx] = qv;
}

extern "C" void kernel_launch(void* const* d_in, const int* in_sizes, int n_in,
                              void* d_out, int out_size) {
    const float* features       = (const float*)d_in[0];
    const float* weights        = (const float*)d_in[1];
    const float* adjacency      = (const float*)d_in[2];
    const float* w_selected     = (const float*)d_in[3];
    const float* w_nbpriors     = (const float*)d_in[4];
    const float* w_nbweights    = (const float*)d_in[5];
    const float* w_nbweights_ew = (const float*)d_in[6];
    const float* w_q_reduc      = (const float*)d_in[7];
    const float* w_q_allembed   = (const float*)d_in[8];
    const float* w_q_action     = (const float*)d_in[9];

    float* out = (float*)d_out;
    float* q = out;                  // [B,N]
    float* emb_out = out + Bb * Nn;  // [B,N,E]

    colsum_kernel<<<dim3(NCH, Bb), 256>>>((const float4*)weights, w_nbpriors);
    base_kernel<<<32, 256>>>(features, w_selected, w_nbweights, w_nbweights_ew);

    dim3 ig(64, Bb);                 // 512 CTAs
    iter_kernel<<<ig, 128>>>(adjacency, 0, emb_out, 0);  // iter 2
    iter_kernel<<<ig, 128>>>(adjacency, 1, emb_out, 0);  // iter 3
    iter_kernel<<<ig, 128>>>(adjacency, 0, emb_out, 0);  // iter 4
    iter_kernel<<<ig, 128>>>(adjacency, 1, emb_out, 1);  // iter 5 (last)

    final_kernel<<<64, 128>>>(emb_out, q, w_q_reduc, w_q_allembed, w_q_action);
}